// round 1
// baseline (speedup 1.0000x reference)
#include <cuda_runtime.h>

#define BB 2
#define LL 512
#define DD 256
#define NN 256
#define DT 64
#define PW 576   // DT + 2*DD

// scratch (device globals — no allocations allowed)
__device__ float g_proj[BB * LL * PW];      // [row, 576] : dt_raw | beta | gamma
__device__ float g_dt  [BB * LL * DD];
__device__ float g_dtx [BB * LL * DD];
__device__ float g_xd  [BB * LL * DD];
__device__ float g_A2  [DD * NN];           // -exp(alpha_log) * log2(e)

__device__ __forceinline__ float ex2_approx(float x) {
    float r;
    asm("ex2.approx.ftz.f32 %0, %1;" : "=f"(r) : "f"(x));
    return r;
}

// ---------------------------------------------------------------------------
// Kernel 0: A2[d][n] = -exp(alpha_log[d][n]) * log2(e)
// ---------------------------------------------------------------------------
__global__ void a2_kernel(const float* __restrict__ alog) {
    int i = blockIdx.x * blockDim.x + threadIdx.x;
    if (i < DD * NN)
        g_A2[i] = -__expf(alog[i]) * 1.4426950408889634f;
}

// ---------------------------------------------------------------------------
// Kernel 1: proj = x @ W_in   ([1024,256] x [256,576] -> [1024,576])
// classic 32x32 smem tile
// ---------------------------------------------------------------------------
__global__ void proj_kernel(const float* __restrict__ x, const float* __restrict__ W) {
    __shared__ float xs[32][33];
    __shared__ float ws[32][33];
    int row = blockIdx.y * 32 + threadIdx.y;
    int col = blockIdx.x * 32 + threadIdx.x;
    float acc = 0.f;
    for (int kt = 0; kt < DD; kt += 32) {
        xs[threadIdx.y][threadIdx.x] = x[row * DD + kt + threadIdx.x];
        ws[threadIdx.y][threadIdx.x] = W[(kt + threadIdx.y) * PW + col];
        __syncthreads();
#pragma unroll
        for (int k = 0; k < 32; k++)
            acc = fmaf(xs[threadIdx.y][k], ws[k][threadIdx.x], acc);
        __syncthreads();
    }
    g_proj[row * PW + col] = acc;
}

// ---------------------------------------------------------------------------
// Kernel 2: dt = softplus(proj[:, :64] @ W_dt + b_dt); dtx = dt*x; xd = x*delta
// one block per row (256 threads, one per d)
// ---------------------------------------------------------------------------
__global__ void dt_kernel(const float* __restrict__ x, const float* __restrict__ Wdt,
                          const float* __restrict__ bdt, const float* __restrict__ delta) {
    int r = blockIdx.x;
    int d = threadIdx.x;
    __shared__ float sp[DT];
    if (d < DT) sp[d] = g_proj[r * PW + d];
    __syncthreads();
    float acc = bdt[d];
#pragma unroll
    for (int k = 0; k < DT; k++)
        acc = fmaf(sp[k], Wdt[k * DD + d], acc);
    // numerically stable softplus
    float dt = fmaxf(acc, 0.f) + log1pf(__expf(-fabsf(acc)));
    float xv = x[r * DD + d];
    int idx = r * DD + d;
    g_dt[idx]  = dt;
    g_dtx[idx] = dt * xv;
    g_xd[idx]  = xv * delta[d];
}

// ---------------------------------------------------------------------------
// Kernel 3: sequential scan over L.
// One warp per (b, d). Lane owns 8 consecutive n (state in registers).
// 128 CTAs x 128 threads = 512 warps -> ~1 warp per SMSP.
// ---------------------------------------------------------------------------
__global__ void __launch_bounds__(128, 1) scan_kernel(float* __restrict__ out) {
    const int warp = threadIdx.x >> 5;
    const int lane = threadIdx.x & 31;
    const int b = blockIdx.x >> 6;                 // 64 CTAs per batch
    const int d = ((blockIdx.x & 63) << 2) + warp; // 4 d per CTA
    const int nb = lane * 8;

    float a2[8], st[8];
#pragma unroll
    for (int j = 0; j < 8; j++) {
        a2[j] = g_A2[d * NN + nb + j];
        st[j] = 0.f;
    }

    const float* projbase = g_proj + (size_t)b * LL * PW;
    const float* dtp  = g_dt  + (size_t)b * LL * DD + d;
    const float* dtxp = g_dtx + (size_t)b * LL * DD + d;
    const float* xdp  = g_xd  + (size_t)b * LL * DD + d;
    float* outp = out + (size_t)b * LL * DD + d;

    // prefetch step 0
    float4 be0, be1, ga0, ga1;
    float dt, dtx;
    {
        const float* pr = projbase;
        be0 = *(const float4*)(pr + DT + nb);
        be1 = *(const float4*)(pr + DT + nb + 4);
        ga0 = *(const float4*)(pr + DT + DD + nb);
        ga1 = *(const float4*)(pr + DT + DD + nb + 4);
        dt  = dtp[0];
        dtx = dtxp[0];
    }

    for (int l = 0; l < LL; l++) {
        // prefetch next step (clamped; last-iter values unused)
        int ln = (l + 1 < LL) ? (l + 1) : (LL - 1);
        const float* pr = projbase + ln * PW;
        float4 nbe0 = *(const float4*)(pr + DT + nb);
        float4 nbe1 = *(const float4*)(pr + DT + nb + 4);
        float4 nga0 = *(const float4*)(pr + DT + DD + nb);
        float4 nga1 = *(const float4*)(pr + DT + DD + nb + 4);
        float ndt  = dtp[ln * DD];
        float ndtx = dtxp[ln * DD];

        float be[8] = {be0.x, be0.y, be0.z, be0.w, be1.x, be1.y, be1.z, be1.w};
        float ga[8] = {ga0.x, ga0.y, ga0.z, ga0.w, ga1.x, ga1.y, ga1.z, ga1.w};

        float acc0 = 0.f, acc1 = 0.f, acc2 = 0.f, acc3 = 0.f;
#pragma unroll
        for (int j = 0; j < 8; j++) {
            float a  = ex2_approx(dt * a2[j]);        // exp(dt*alpha)
            float bb = dtx * be[j];
            st[j] = fmaf(a, st[j], bb);
            float p = st[j] * ga[j];
            if ((j & 3) == 0) acc0 += p;
            else if ((j & 3) == 1) acc1 += p;
            else if ((j & 3) == 2) acc2 += p;
            else acc3 += p;
        }
        float y = (acc0 + acc1) + (acc2 + acc3);
#pragma unroll
        for (int off = 16; off > 0; off >>= 1)
            y += __shfl_xor_sync(0xffffffffu, y, off);

        if (lane == 0)
            outp[l * DD] = y + xdp[l * DD];

        be0 = nbe0; be1 = nbe1; ga0 = nga0; ga1 = nga1;
        dt = ndt; dtx = ndtx;
    }
}

// ---------------------------------------------------------------------------
extern "C" void kernel_launch(void* const* d_in, const int* in_sizes, int n_in,
                              void* d_out, int out_size) {
    const float* x      = (const float*)d_in[0];  // [2,512,256]
    const float* W_in   = (const float*)d_in[1];  // [256,576]
    const float* W_dt   = (const float*)d_in[2];  // [64,256]
    const float* b_dt   = (const float*)d_in[3];  // [256]
    const float* alog   = (const float*)d_in[4];  // [256,256]
    const float* delta  = (const float*)d_in[5];  // [256]
    float* out = (float*)d_out;                   // [2,512,256]

    a2_kernel<<<(DD * NN + 255) / 256, 256>>>(alog);

    dim3 pgrid(PW / 32, (BB * LL) / 32);
    dim3 pblk(32, 32);
    proj_kernel<<<pgrid, pblk>>>(x, W_in);

    dt_kernel<<<BB * LL, DD>>>(x, W_dt, b_dt, delta);

    scan_kernel<<<BB * 64, 128>>>(out);
}